// round 15
// baseline (speedup 1.0000x reference)
#include <cuda_runtime.h>
#include <cuda_bf16.h>

// Problem constants
#define BB 8
#define NN 65536
#define PP 12
#define GG 64
#define G3 (GG*GG*GG)               // 262144
#define THREADS 256
#define NBLOCKS ((BB*NN)/THREADS)   // 2048 (also the grid size)
#define NCELLS  (BB*G3)             // 2097152
#define NPACKERS 148                // one packer block per SM (wave-1 resident)
#define SLICE ((G3 + NPACKERS - 1) / NPACKERS)   // 1772 cells per packer per batch

// Scratch (static device arrays — no dynamic allocation anywhere)
__device__ float4 g_packed[NCELLS];   // (cp.x, cp.y, cp.z, 1-voxel) per cell; 32MB
__device__ float  g_partials[NBLOCKS];
__device__ int    g_counter = 0;      // last-block ticket; self-resets each launch
__device__ int    g_ready[BB];        // per-batch pack completion count; self-resets

// ---------------------------------------------------------------------------
// Fused kernel (single launch), overlap v2.
//
// R13 lesson: consumers polled the ready flag with atomicAdd(&x,0) — an L2
// RMW serialized per-address (~32cyc/op); ~740 pollers saturated the flag's
// atomic pipe and starved the packers. v2 polls with a PLAIN VOLATILE LOAD
// (ordinary L2 read, broadcastable, no serialization) + longer nanosleep.
// Acquire = threadfence after observing the flag; release side unchanged
// (fence + one atomicAdd per packer per batch: 1184 RMWs total).
//
// PACK phase (blocks 0..147, wave-1 resident): batch 0 first, then 1..7;
// each packer streams its 1772-cell slice with the R10-proven scalar pattern
// (coalesced 12B stride). Packers wait on nothing -> deadlock-free.
//
// MAIN phase (all 2048 blocks): bit-identical to R12's proven pipeline.
// plane = f >> 16 reshape mapping; ONE unconditional LDG.128 per (pt,plane)
// into the single-sector packed row; term = dist^2 * mask (mask in {0,1});
// exact sqrtf/div plane normalization in shared; deterministic reductions.
// ---------------------------------------------------------------------------
__global__ __launch_bounds__(THREADS, 6)
void sym_plane_loss_fused(const float* __restrict__ voxel,
                          const float* __restrict__ points,
                          const float* __restrict__ cp,
                          const float* __restrict__ planes,
                          float* __restrict__ out)
{
    const int bid = blockIdx.x;
    const int tid = threadIdx.x;

    // ================= PACK phase (blocks 0..147) =================
    if (bid < NPACKERS) {
        #pragma unroll 1
        for (int ph = 0; ph < BB; ph++) {
            const int start = bid * SLICE;
            const int end   = (start + SLICE < G3) ? (start + SLICE) : G3;
            for (int c0 = start + tid; c0 < end; c0 += THREADS) {
                const int c = ph * G3 + c0;
                const float v  = voxel[c];
                const float cx = cp[c*3 + 0];
                const float cy = cp[c*3 + 1];
                const float cz = cp[c*3 + 2];
                g_packed[c] = make_float4(cx, cy, cz, 1.0f - v);
            }
            __syncthreads();            // whole block's slice written
            if (tid == 0) {
                __threadfence();        // release: packed data visible
                atomicAdd(&g_ready[ph], 1);
            }
        }
    }

    // ================= MAIN phase (all blocks) =================
    const int t  = bid * THREADS + tid;   // 0 .. B*N-1
    const int b  = t >> 16;               // N = 65536; constant per block
    const int pt = t & 0xFFFF;

    // point load issued early (overlaps spin/barrier below)
    const float px = __ldg(points + t*3 + 0);
    const float py = __ldg(points + t*3 + 1);
    const float pz = __ldg(points + t*3 + 2);

    // normalize this batch's 12 planes into shared (exact math)
    __shared__ float4 s_planes[PP];
    if (tid < PP) {
        const int i = b * PP + tid;
        const float nx = planes[i*4+0];
        const float ny = planes[i*4+1];
        const float nz = planes[i*4+2];
        const float d  = planes[i*4+3];
        const float norm = sqrtf(nx*nx + ny*ny + nz*nz);
        s_planes[tid] = make_float4(nx/norm, ny/norm, nz/norm, d/norm);
    }

    // spin until this batch's pack is complete: VOLATILE LOAD poll (no RMW)
    if (tid == 0) {
        const volatile int* rdy = (const volatile int*)&g_ready[b];
        while (*rdy < NPACKERS) __nanosleep(256);
        __threadfence();   // acquire: packed data ordered before gathers
    }
    __syncthreads();   // covers s_planes + spin release

    const float4* __restrict__ pk_b = g_packed + b * G3;
    const int base_f = pt * PP;

    int idxs[PP];

    // Phase A: reflections -> cell indices (ALU only)
    #pragma unroll
    for (int k = 0; k < PP; k++) {
        const int f     = base_f + k;
        const float4 n4 = s_planes[f >> 16];

        const float dot = px*n4.x + py*n4.y + pz*n4.z;
        const float s   = 2.0f * (dot + n4.w);
        const float rx  = px - s * n4.x;
        const float ry  = py - s * n4.y;
        const float rz  = pz - s * n4.z;

        const int ix = (int)ceilf(__fadd_rn(__fmul_rn(__fadd_rn(rx, 0.5f), (float)GG), -0.5f));
        const int iy = (int)ceilf(__fadd_rn(__fmul_rn(__fadd_rn(ry, 0.5f), (float)GG), -0.5f));
        const int iz = (int)ceilf(__fadd_rn(__fmul_rn(__fadd_rn(rz, 0.5f), (float)GG), -0.5f));

        int idx = ix * (GG*GG) + iy * GG + iz;
        idx = min(max(idx, 0), G3 - 1);
        idxs[k] = idx;
    }

    // Phase B: 12 unconditional packed gathers + accumulate (2 x 6, MLP=6)
    float acc = 0.0f;
    #pragma unroll
    for (int h = 0; h < 2; h++) {
        float4 q[6];
        #pragma unroll
        for (int j = 0; j < 6; j++) {
            q[j] = __ldg(pk_b + idxs[h*6 + j]);
        }
        #pragma unroll
        for (int j = 0; j < 6; j++) {
            const int k     = h*6 + j;
            const int f     = base_f + k;
            const float4 n4 = s_planes[f >> 16];
            const float dot = px*n4.x + py*n4.y + pz*n4.z;   // identical expr as Phase A
            const float s   = 2.0f * (dot + n4.w);
            const float rx  = px - s * n4.x;
            const float ry  = py - s * n4.y;
            const float rz  = pz - s * n4.z;

            const float dx = rx - q[j].x;
            const float dy = ry - q[j].y;
            const float dz = rz - q[j].z;
            acc += (dx*dx + dy*dy + dz*dz) * q[j].w;   // mask in {0,1}: exact
        }
    }

    // deterministic block reduction
    __shared__ float sdata[THREADS];
    __shared__ bool  s_is_last;
    sdata[tid] = acc;
    __syncthreads();
    #pragma unroll
    for (int stride = THREADS/2; stride >= 32; stride >>= 1) {
        if (tid < stride) sdata[tid] += sdata[tid + stride];
        __syncthreads();
    }
    if (tid < 32) {
        float w = sdata[tid];
        #pragma unroll
        for (int off = 16; off > 0; off >>= 1)
            w += __shfl_down_sync(0xFFFFFFFF, w, off);
        if (tid == 0) {
            g_partials[bid] = w;
            __threadfence();
            const int ticket = atomicAdd(&g_counter, 1);
            s_is_last = (ticket == NBLOCKS - 1);
        }
    }
    __syncthreads();

    // last block: fixed-order final reduction + state reset (deterministic)
    if (s_is_last) {
        float sacc = 0.0f;
        #pragma unroll
        for (int i = tid; i < NBLOCKS; i += THREADS)   // 8 fixed-order adds
            sacc += g_partials[i];
        sdata[tid] = sacc;
        __syncthreads();
        #pragma unroll
        for (int stride = THREADS/2; stride >= 32; stride >>= 1) {
            if (tid < stride) sdata[tid] += sdata[tid + stride];
            __syncthreads();
        }
        if (tid < 32) {
            float w = sdata[tid];
            #pragma unroll
            for (int off = 16; off > 0; off >>= 1)
                w += __shfl_down_sync(0xFFFFFFFF, w, off);
            if (tid == 0) {
                out[0] = w / (float)(BB * PP);
                g_counter = 0;                 // reset for next replay
                #pragma unroll
                for (int i = 0; i < BB; i++) g_ready[i] = 0;
            }
        }
    }
}

// ---------------------------------------------------------------------------
// Inputs (metadata order = setup_inputs dict order):
//   d_in[0] voxel          (B, G, G, G)   float32
//   d_in[1] points         (B, N, 3)      float32
//   d_in[2] closest_points (B, G^3, 3)    float32
//   d_in[3] planes         (B, P, 4)      float32
// Output: scalar float32
// ---------------------------------------------------------------------------
extern "C" void kernel_launch(void* const* d_in, const int* in_sizes, int n_in,
                              void* d_out, int out_size)
{
    const float* voxel  = (const float*)d_in[0];
    const float* points = (const float*)d_in[1];
    const float* cp     = (const float*)d_in[2];
    const float* planes = (const float*)d_in[3];
    float* out = (float*)d_out;

    sym_plane_loss_fused<<<NBLOCKS, THREADS>>>(voxel, points, cp, planes, out);
}

// round 16
// speedup vs baseline: 1.1507x; 1.1507x over previous
#include <cuda_runtime.h>
#include <cuda_bf16.h>

// Problem constants
#define BB 8
#define NN 65536
#define PP 12
#define GG 64
#define G3 (GG*GG*GG)               // 262144
#define THREADS 256
#define NBLOCKS ((BB*NN)/THREADS)   // 2048
#define NCELLS  (BB*G3)             // 2097152

// Scratch (static device arrays — no dynamic allocation anywhere)
__device__ float4 g_packed[NCELLS];   // (cp.x, cp.y, cp.z, 1-voxel) per cell; 32MB
__device__ float  g_partials[NBLOCKS];
__device__ int    g_counter = 0;      // last-block ticket; self-resets each launch

// ---------------------------------------------------------------------------
// Kernel 1 (prep): pack (cp, mask) into one 16B row per cell.
// Scalar coalesced form — measured at the 64MB/~12.5TB/s streaming floor
// (~5.1us). (The 4-cell "vectorized" variant had 48B inter-thread stride ->
// 3x the L1tex wavefronts and ~12us; disproven in R11.)
// mask = 1 - v is exact (v in {0,1}).
// ---------------------------------------------------------------------------
__global__ __launch_bounds__(THREADS)
void pack_kernel(const float* __restrict__ voxel,
                 const float* __restrict__ cp)
{
    const int c = blockIdx.x * THREADS + threadIdx.x;   // 0 .. NCELLS-1
    const float v  = voxel[c];
    const float cx = cp[c*3 + 0];
    const float cy = cp[c*3 + 1];
    const float cz = cp[c*3 + 2];
    g_packed[c] = make_float4(cx, cy, cz, 1.0f - v);
}

// ---------------------------------------------------------------------------
// Kernel 2 (main): one thread per (b, point); each thread owns the 12 flat
// positions f = pt*12+k of the reference's (b, p*n) flattening, so
// plane = f >> 16 (N = 2^16) — reproduces the reference's reshape
// reinterpretation of the broadcast (b,n,p,3) array into (b,p,n,3).
//
// ONE unconditional LDG.128 per (pt,plane): packed row = cp + {0,1} mask in
// exactly one 32B L2 sector (validated in R10: -29% on the main kernel;
// measured ~20.6-20.9us ~= 9.8TB/s of L2 gather sectors, ~80% of LTS cap).
// term = (dx^2+dy^2+dz^2) * mask  ==  conditional skip, exactly.
//
// Planes normalized once per block in shared with EXACT reference arithmetic
// (sqrtf + division) — R5 proved approximate normalization flips ceil cells.
// Reflection recomputed at consume time from the same shared values with the
// same expression (bit-identical; validated R8-R15, rel_err 1.371e-7).
// ---------------------------------------------------------------------------
__global__ __launch_bounds__(THREADS, 6)
void sym_plane_loss_kernel(const float* __restrict__ points,
                           const float* __restrict__ planes,
                           float* __restrict__ out)
{
    const int t  = blockIdx.x * THREADS + threadIdx.x;   // 0 .. B*N-1
    const int b  = t >> 16;            // N = 65536; constant within a block
    const int pt = t & 0xFFFF;

    // ---- issue point load first: overlaps the barrier below ----
    const float px = __ldg(points + t*3 + 0);
    const float py = __ldg(points + t*3 + 1);
    const float pz = __ldg(points + t*3 + 2);

    // ---- normalize this batch's 12 planes into shared (exact math) ----
    __shared__ float4 s_planes[PP];
    if (threadIdx.x < PP) {
        const int i = b * PP + threadIdx.x;
        const float nx = planes[i*4+0];
        const float ny = planes[i*4+1];
        const float nz = planes[i*4+2];
        const float d  = planes[i*4+3];
        const float norm = sqrtf(nx*nx + ny*ny + nz*nz);
        s_planes[threadIdx.x] = make_float4(nx/norm, ny/norm, nz/norm, d/norm);
    }
    __syncthreads();

    const float4* __restrict__ pk_b = g_packed + b * G3;
    const int base_f = pt * PP;

    int idxs[PP];

    // ---- Phase A: reflections -> cell indices (ALU only) ----
    #pragma unroll
    for (int k = 0; k < PP; k++) {
        const int f     = base_f + k;
        const float4 n4 = s_planes[f >> 16];

        const float dot = px*n4.x + py*n4.y + pz*n4.z;
        const float s   = 2.0f * (dot + n4.w);
        const float rx  = px - s * n4.x;
        const float ry  = py - s * n4.y;
        const float rz  = pz - s * n4.z;

        const int ix = (int)ceilf(__fadd_rn(__fmul_rn(__fadd_rn(rx, 0.5f), (float)GG), -0.5f));
        const int iy = (int)ceilf(__fadd_rn(__fmul_rn(__fadd_rn(ry, 0.5f), (float)GG), -0.5f));
        const int iz = (int)ceilf(__fadd_rn(__fmul_rn(__fadd_rn(rz, 0.5f), (float)GG), -0.5f));

        int idx = ix * (GG*GG) + iy * GG + iz;
        idx = min(max(idx, 0), G3 - 1);
        idxs[k] = idx;
    }

    // ---- Phase B: 12 unconditional packed gathers + accumulate.
    //      Two half-batches of 6 (MLP=6/wave) keep live regs bounded. ----
    float acc = 0.0f;
    #pragma unroll
    for (int h = 0; h < 2; h++) {
        float4 q[6];
        #pragma unroll
        for (int j = 0; j < 6; j++) {
            q[j] = __ldg(pk_b + idxs[h*6 + j]);
        }
        #pragma unroll
        for (int j = 0; j < 6; j++) {
            const int k     = h*6 + j;
            const int f     = base_f + k;
            const float4 n4 = s_planes[f >> 16];
            const float dot = px*n4.x + py*n4.y + pz*n4.z;   // identical expr as Phase A
            const float s   = 2.0f * (dot + n4.w);
            const float rx  = px - s * n4.x;
            const float ry  = py - s * n4.y;
            const float rz  = pz - s * n4.z;

            const float dx = rx - q[j].x;
            const float dy = ry - q[j].y;
            const float dz = rz - q[j].z;
            acc += (dx*dx + dy*dy + dz*dz) * q[j].w;   // mask in {0,1}: exact
        }
    }

    // ---- deterministic block reduction ----
    __shared__ float sdata[THREADS];
    __shared__ bool  s_is_last;
    sdata[threadIdx.x] = acc;
    __syncthreads();
    #pragma unroll
    for (int stride = THREADS/2; stride >= 32; stride >>= 1) {
        if (threadIdx.x < stride) sdata[threadIdx.x] += sdata[threadIdx.x + stride];
        __syncthreads();
    }
    if (threadIdx.x < 32) {
        float w = sdata[threadIdx.x];
        #pragma unroll
        for (int off = 16; off > 0; off >>= 1)
            w += __shfl_down_sync(0xFFFFFFFF, w, off);
        if (threadIdx.x == 0) {
            g_partials[blockIdx.x] = w;
            __threadfence();
            const int ticket = atomicAdd(&g_counter, 1);
            s_is_last = (ticket == NBLOCKS - 1);
        }
    }
    __syncthreads();

    // ---- last block: fixed-order final reduction (deterministic) ----
    if (s_is_last) {
        float sacc = 0.0f;
        #pragma unroll
        for (int i = threadIdx.x; i < NBLOCKS; i += THREADS)   // 8 fixed-order adds
            sacc += g_partials[i];
        sdata[threadIdx.x] = sacc;
        __syncthreads();
        #pragma unroll
        for (int stride = THREADS/2; stride >= 32; stride >>= 1) {
            if (threadIdx.x < stride) sdata[threadIdx.x] += sdata[threadIdx.x + stride];
            __syncthreads();
        }
        if (threadIdx.x < 32) {
            float w = sdata[threadIdx.x];
            #pragma unroll
            for (int off = 16; off > 0; off >>= 1)
                w += __shfl_down_sync(0xFFFFFFFF, w, off);
            if (threadIdx.x == 0) {
                out[0] = w / (float)(BB * PP);
                g_counter = 0;   // reset for next graph replay
            }
        }
    }
}

// ---------------------------------------------------------------------------
// Inputs (metadata order = setup_inputs dict order):
//   d_in[0] voxel          (B, G, G, G)   float32
//   d_in[1] points         (B, N, 3)      float32
//   d_in[2] closest_points (B, G^3, 3)    float32
//   d_in[3] planes         (B, P, 4)      float32
// Output: scalar float32
// ---------------------------------------------------------------------------
extern "C" void kernel_launch(void* const* d_in, const int* in_sizes, int n_in,
                              void* d_out, int out_size)
{
    const float* voxel  = (const float*)d_in[0];
    const float* points = (const float*)d_in[1];
    const float* cp     = (const float*)d_in[2];
    const float* planes = (const float*)d_in[3];
    float* out = (float*)d_out;

    pack_kernel<<<NCELLS/THREADS, THREADS>>>(voxel, cp);
    sym_plane_loss_kernel<<<NBLOCKS, THREADS>>>(points, planes, out);
}